// round 15
// baseline (speedup 1.0000x reference)
#include <cuda_runtime.h>
#include <cstdint>

// ---------------- constants ----------------
#define TT    9
#define BB    8
#define CC    256
#define HWHW  3136
#define PIX   8
#define NTHREADS 512
#define TILES_PER_B 392          // 3136/8
#define NTILES 3136
#define GRID  296                // 2 persistent CTAs per SM

// ---------------- main kernel: zero-staging direct-LDG ----------------
__global__ __launch_bounds__(NTHREADS, 2)
void tfma_ldg_kernel(const float* __restrict__ seq,
                     const float* __restrict__ wptr,
                     const float* __restrict__ bptr,   // unused: softmax shift-invariant
                     const float* __restrict__ gptr,
                     float* __restrict__ out)
{
    __shared__ float part[16 * 72];   // [16 warps][9t x 8p]
    __shared__ float scor[72];

    const int tid  = threadIdx.x;
    const int lane = tid & 31;
    const int wrp  = tid >> 5;          // 0..15
    const int p    = tid & (PIX - 1);   // 0..7
    const int cg   = tid >> 3;          // 0..63

    // static balanced tile range over 3136 tiles (296 CTAs)
    const int g0  = (int)(((long)blockIdx.x * NTILES) / GRID);
    const int g1  = (int)(((long)(blockIdx.x + 1) * NTILES) / GRID);
    const int cnt = g1 - g0;
    if (cnt <= 0) return;

    // w_other only: w_center + bias shift all t equally -> softmax-invariant.
    float wot[4];
    #pragma unroll
    for (int ci = 0; ci < 4; ++ci)
        wot[ci] = wptr[CC + cg + (ci << 6)];
    const float gamma = gptr[0];
    (void)bptr;

    #pragma unroll 1
    for (int k = 0; k < cnt; ++k) {
        const int g    = g0 + k;
        const int bidx = g / TILES_PER_B;
        const int pix0 = (g % TILES_PER_B) * PIX;

        // per-thread element stream: (t, c, pix0+p)
        const float* base = seq + (size_t)bidx * CC * HWHW + pix0 + p;

        // ---- load the 36 values this thread consumes (coalesced 32B) ----
        float rv[4][TT];
        #pragma unroll
        for (int ci = 0; ci < 4; ++ci) {
            const int c = cg + (ci << 6);
            const float* gp = base + (size_t)c * HWHW;
            #pragma unroll
            for (int t = 0; t < TT; ++t)
                rv[ci][t] = gp[(size_t)t * BB * CC * HWHW];
        }

        // ---- score partials over this thread's 4 channels ----
        float acc[TT];
        #pragma unroll
        for (int t = 0; t < TT; ++t) {
            float s = 0.f;
            #pragma unroll
            for (int ci = 0; ci < 4; ++ci)
                s = fmaf(rv[ci][t], wot[ci], s);
            acc[t] = s;
        }
        // warp reduce: xor8 + xor16 combine the warp's 4 c-groups (same p)
        #pragma unroll
        for (int t = 0; t < TT; ++t) {
            acc[t] += __shfl_xor_sync(0xffffffffu, acc[t], 8);
            acc[t] += __shfl_xor_sync(0xffffffffu, acc[t], 16);
        }
        if (lane < PIX) {
            #pragma unroll
            for (int t = 0; t < TT; ++t)
                part[wrp * 72 + t * PIX + lane] = acc[t];
        }
        __syncthreads();                   // bar1: partials visible

        // ---- cross-warp reduce: 72 threads x 16 values ----
        if (tid < 72) {
            float s = 0.f;
            #pragma unroll
            for (int w = 0; w < 16; ++w) s += part[w * 72 + tid];
            scor[tid] = s;
        }
        __syncthreads();                   // bar2: scor visible

        // ---- softmax (shift-free) + attended sum + residual ----
        {
            float a[TT];
            float m = -1e30f;
            #pragma unroll
            for (int t = 0; t < TT; ++t) {
                a[t] = scor[t * PIX + p];
                m = fmaxf(m, a[t]);
            }
            float sum = 0.f;
            #pragma unroll
            for (int t = 0; t < TT; ++t) {
                a[t] = __expf(a[t] - m);
                sum += a[t];
            }
            const float inv = 1.f / sum;
            #pragma unroll
            for (int t = 0; t < TT; ++t) a[t] *= inv;

            float* ob = out + (size_t)bidx * CC * HWHW + pix0 + p;
            #pragma unroll
            for (int ci = 0; ci < 4; ++ci) {
                const int c = cg + (ci << 6);
                float s = 0.f;
                #pragma unroll
                for (int t = 0; t < TT; ++t)
                    s = fmaf(a[t], rv[ci][t], s);
                ob[(size_t)c * HWHW] = rv[ci][TT / 2] + gamma * s;
            }
        }
        // Reuse safety with only 2 barriers:
        //  - part(k+1) is written after the writer passed bar2(k); all reads
        //    of part(k) (the reduce) completed before bar2(k). Safe.
        //  - scor(k+1) is written after bar1(k+1) completes, which requires
        //    every thread to have arrived there -- i.e. to have finished its
        //    softmax reads of scor(k). Safe.
    }
}

extern "C" void kernel_launch(void* const* d_in, const int* in_sizes, int n_in,
                              void* d_out, int out_size)
{
    (void)in_sizes; (void)n_in; (void)out_size;
    const float* seq   = (const float*)d_in[0];
    const float* w     = (const float*)d_in[1];
    const float* bv    = (const float*)d_in[2];
    const float* gamma = (const float*)d_in[3];
    float* out = (float*)d_out;

    tfma_ldg_kernel<<<GRID, NTHREADS>>>(seq, w, bv, gamma, out);
}

// round 16
// speedup vs baseline: 1.6967x; 1.6967x over previous
#include <cuda_runtime.h>
#include <cstdint>

// ---------------- constants ----------------
#define TT    9
#define BB    8
#define CC    256
#define HWHW  3136
#define PIX   16
#define NTHREADS 512
#define TILES_PER_B 196          // 3136/16
#define GRID  148                // persistent, 1 CTA/SM

#define H0_T  4                  // t = 0..3  (A half)
#define H1_T  5                  // t = 4..8  (B half)
#define A_FLOATS (H0_T*CC*PIX)   // 16384 floats = 65536 B
#define B_FLOATS (H1_T*CC*PIX)   // 20480 floats = 81920 B

#define NWARP 16
#define PPITCH 20                // part2 row pitch (16 + 4 pad), 80B (16B aligned)

// SMEM layout (float offsets)
#define OFF_A    0
#define OFF_B    (A_FLOATS)                  // 16384
#define OFF_PART (A_FLOATS + B_FLOATS)       // 36864  [144][PPITCH] transposed
#define OFF_SCOR (OFF_PART + 144*PPITCH)     // 39744  [144]
#define SMEM_FLOATS (OFF_SCOR + 144)
#define SMEM_BYTES  (SMEM_FLOATS * 4)        // 159552 B

// Coalesced half loader (512 threads): thread = (q = tid&3, rb = tid>>2).
// A warp covers 8 consecutive c-rows, full 64B width -> 8 lines/warp-op.
// Each thread handles rows rb and rb+128 for nt t-slices.
__device__ __forceinline__ void cp_half(uint32_t dst_bytes,
                                        const float* __restrict__ src, // seq + b*CC*HW + pix0
                                        int q, int rb, int t0, int nt)
{
    #pragma unroll
    for (int j = 0; j < nt; ++j) {
        const float* g = src + (size_t)(t0 + j) * BB * CC * HWHW + (size_t)rb * HWHW + q * 4;
        uint32_t s = dst_bytes + (uint32_t)(((j * CC + rb) * PIX + q * 4) * 4);
        asm volatile("cp.async.cg.shared.global [%0], [%1], 16;\n"
                     :: "r"(s), "l"(g) : "memory");
        g += (size_t)128 * HWHW;            // row rb+128
        s += (uint32_t)(128 * PIX * 4);
        asm volatile("cp.async.cg.shared.global [%0], [%1], 16;\n"
                     :: "r"(s), "l"(g) : "memory");
    }
}

#define COMMIT() asm volatile("cp.async.commit_group;\n" ::: "memory")
#define WAITG(n) asm volatile("cp.async.wait_group %0;\n" :: "n"(n) : "memory")

// ---------------- main kernel ----------------
__global__ __launch_bounds__(NTHREADS)      // 128-register budget
void tfma_r14_kernel(const float* __restrict__ seq,
                     const float* __restrict__ wptr,
                     const float* __restrict__ bptr,   // unused: softmax shift-invariant
                     const float* __restrict__ gptr,
                     float* __restrict__ out)
{
    extern __shared__ float sm[];
    float* part = sm + OFF_PART;   // [144][PPITCH], transposed: row = slot, col = warp
    float* scor = sm + OFF_SCOR;
    const uint32_t smem_base = (uint32_t)__cvta_generic_to_shared(sm);
    const uint32_t dstA = smem_base;
    const uint32_t dstB = smem_base + A_FLOATS * 4;

    const int tid  = threadIdx.x;
    const int lane = tid & 31;
    const int wrp  = tid >> 5;          // 0..15
    const int p    = tid & (PIX - 1);   // 0..15
    const int cg   = tid >> 4;          // 0..31 (8 channels each)
    const int q    = tid & 3;           // load quarter of a 64B row
    const int rb   = tid >> 2;          // load row 0..127 (+128)

    // static balanced tile range over 1568 tiles
    const int g0  = (int)(((long)blockIdx.x * 392) / 37);
    const int g1  = (int)(((long)(blockIdx.x + 1) * 392) / 37);
    const int cnt = g1 - g0;
    if (cnt <= 0) return;

    // w_other only: w_center + bias shift all t equally -> softmax-invariant.
    float wot[8];
    #pragma unroll
    for (int ci = 0; ci < 8; ++ci)
        wot[ci] = wptr[CC + cg + (ci << 5)];
    const float gamma = gptr[0];
    (void)bptr;

    // prologue: A(g0), B(g0)
    {
        const int bidx = g0 / TILES_PER_B;
        const float* src = seq + (size_t)bidx * CC * HWHW + (g0 % TILES_PER_B) * PIX;
        cp_half(dstA, src, q, rb, 0, H0_T);
        COMMIT();
        cp_half(dstB, src, q, rb, H0_T, H1_T);
        COMMIT();
    }

    #pragma unroll 1
    for (int k = 0; k < cnt; ++k) {
        const int g    = g0 + k;
        const int bidx = g / TILES_PER_B;
        const int pix0 = (g % TILES_PER_B) * PIX;

        const int gn      = g + 1;
        const float* nsrc = seq + (size_t)(gn / TILES_PER_B) * CC * HWHW
                                + (gn % TILES_PER_B) * PIX;
        const bool more = (k + 1 < cnt);

        float rv[8][TT];
        float acc[TT];
        #pragma unroll
        for (int t = 0; t < TT; ++t) acc[t] = 0.f;

        // ---- wait A(k): exactly one group (B(k)) may remain pending ----
        WAITG(1);
        __syncthreads();                       // bar0: A visible to all

        #pragma unroll
        for (int ci = 0; ci < 8; ++ci) {
            const int c = cg + (ci << 5);
            #pragma unroll
            for (int t = 0; t < H0_T; ++t) {
                rv[ci][t] = sm[(t * CC + c) * PIX + p];
                acc[t] = fmaf(rv[ci][t], wot[ci], acc[t]);
            }
        }

        // ---- wait B(k) ----
        WAITG(0);
        __syncthreads();                       // bar1: A consumed by all + B visible

        if (more) cp_half(dstA, nsrc, q, rb, 0, H0_T);   // refill A(k+1)
        COMMIT();

        #pragma unroll
        for (int ci = 0; ci < 8; ++ci) {
            const int c = cg + (ci << 5);
            #pragma unroll
            for (int t = H0_T; t < TT; ++t) {
                rv[ci][t] = sm[OFF_B + ((t - H0_T) * CC + c) * PIX + p];
                acc[t] = fmaf(rv[ci][t], wot[ci], acc[t]);
            }
        }
        // warp partials: xor16 combines the warp's two c-groups (same p)
        #pragma unroll
        for (int t = 0; t < TT; ++t)
            acc[t] += __shfl_xor_sync(0xffffffffu, acc[t], 16);
        // transposed store: part[t*16 + p][wrp]
        if (lane < PIX) {
            #pragma unroll
            for (int t = 0; t < TT; ++t)
                part[(t * PIX + lane) * PPITCH + wrp] = acc[t];
        }
        __syncthreads();                       // bar2: B consumed + partials visible

        if (more) cp_half(dstB, nsrc, q, rb, H0_T, H1_T);  // refill B(k+1)
        COMMIT();

        // ---- cross-warp reduce: 144 threads, vectorized LDS.128 ----
        if (tid < 144) {
            const float4* row = (const float4*)(part + tid * PPITCH);
            float4 v0 = row[0], v1 = row[1], v2 = row[2], v3 = row[3];
            scor[tid] = ((v0.x + v0.y) + (v0.z + v0.w))
                      + ((v1.x + v1.y) + (v1.z + v1.w))
                      + ((v2.x + v2.y) + (v2.z + v2.w))
                      + ((v3.x + v3.y) + (v3.z + v3.w));
        }
        __syncthreads();                       // bar3: scor visible

        // ---- softmax (shift-free) + attended sum + residual ----
        {
            float a[TT];
            float m = -1e30f;
            #pragma unroll
            for (int t = 0; t < TT; ++t) {
                a[t] = scor[t * PIX + p];
                m = fmaxf(m, a[t]);
            }
            float sum = 0.f;
            #pragma unroll
            for (int t = 0; t < TT; ++t) {
                a[t] = __expf(a[t] - m);
                sum += a[t];
            }
            const float inv = 1.f / sum;
            #pragma unroll
            for (int t = 0; t < TT; ++t) a[t] *= inv;

            float* ob = out + (size_t)bidx * CC * HWHW + pix0 + p;
            #pragma unroll
            for (int ci = 0; ci < 8; ++ci) {
                const int c = cg + (ci << 5);
                float s = 0.f;
                #pragma unroll
                for (int t = 0; t < TT; ++t)
                    s = fmaf(a[t], rv[ci][t], s);
                ob[(size_t)c * HWHW] = rv[ci][TT / 2] + gamma * s;
            }
        }
        // Reuse safety (no trailing barrier), as in R12:
        //  - part(k+1) written after bar1(k+1) > bar3(k) >= reduce(k) reads.
        //  - scor(k+1) written after bar2(k+1) > bar0(k+1) >= softmax(k) reads.
        //  - A(k+1) issued after bar1(k); B(k+1) after bar2(k).
        //  - exactly 2 groups committed per iteration -> WAITG(1)/WAITG(0) exact.
    }
}

extern "C" void kernel_launch(void* const* d_in, const int* in_sizes, int n_in,
                              void* d_out, int out_size)
{
    (void)in_sizes; (void)n_in; (void)out_size;
    const float* seq   = (const float*)d_in[0];
    const float* w     = (const float*)d_in[1];
    const float* bv    = (const float*)d_in[2];
    const float* gamma = (const float*)d_in[3];
    float* out = (float*)d_out;

    cudaFuncSetAttribute(tfma_r14_kernel,
                         cudaFuncAttributeMaxDynamicSharedMemorySize, SMEM_BYTES);
    tfma_r14_kernel<<<GRID, NTHREADS, SMEM_BYTES>>>(seq, w, bv, gamma, out);
}